// round 16
// baseline (speedup 1.0000x reference)
#include <cuda_runtime.h>
#include <cuda_bf16.h>
#include <cstdint>

// Problem dims (fixed by the dataset)
#define BB   4
#define TQ   256
#define TV   1024
#define DD   512
#define AA   128

// Scratch buffers (device globals: allocation-free)
__device__ float g_K[BB * TV * AA];        // 2 MB
__device__ float g_Q[BB * TQ * AA];        // 0.5 MB
__device__ float g_attn[BB * TQ * TV];     // 4 MB (tf32-rounded at write)
__device__ float g_inT[BB * TV * DD];      // 8 MB   inputs, tf32-rounded
__device__ float g_cxT[BB * TQ * DD];      // 2 MB   context, tf32-rounded
__device__ float g_WkT[DD * AA];           // 256 KB
__device__ float g_WqT[DD * AA];           // 256 KB

// ---------------------------------------------------------------------------
// fast math helpers
// ---------------------------------------------------------------------------
__device__ __forceinline__ float fast_ex2(float x) {
    float y;
    asm("ex2.approx.f32 %0, %1;" : "=f"(y) : "f"(x));
    return y;
}
__device__ __forceinline__ float ftanh(float x) {
    float y;
    asm("tanh.approx.f32 %0, %1;" : "=f"(y) : "f"(x));
    return y;
}
// cp.async helpers (16B)
__device__ __forceinline__ void cp16(void* dst_smem, const void* src_gmem) {
    unsigned d = (unsigned)__cvta_generic_to_shared(dst_smem);
    asm volatile("cp.async.ca.shared.global [%0], [%1], 16;" :: "r"(d), "l"(src_gmem));
}
__device__ __forceinline__ void cp_commit() {
    asm volatile("cp.async.commit_group;");
}
__device__ __forceinline__ void cp_wait0() {
    asm volatile("cp.async.wait_group 0;");
}
// tf32 round (rna)
__device__ __forceinline__ float round_tf32(float x) {
    uint32_t r;
    asm("cvt.rna.tf32.f32 %0, %1;" : "=r"(r) : "f"(x));
    return __uint_as_float(r);
}
__device__ __forceinline__ void mma_tf32(float4& d,
    uint32_t a0, uint32_t a1, uint32_t a2, uint32_t a3,
    uint32_t b0, uint32_t b1)
{
    asm volatile(
        "mma.sync.aligned.m16n8k8.row.col.f32.tf32.tf32.f32 "
        "{%0,%1,%2,%3}, {%4,%5,%6,%7}, {%8,%9}, {%0,%1,%2,%3};"
        : "+f"(d.x), "+f"(d.y), "+f"(d.z), "+f"(d.w)
        : "r"(a0), "r"(a1), "r"(a2), "r"(a3), "r"(b0), "r"(b1));
}

// ---------------------------------------------------------------------------
// Kernel 0: round inputs/context/Wk/Wq to tf32 (rna) so the GEMM mainloops
// can feed raw register bits to mma (bit-exact tf32, no per-use cvt).
// ---------------------------------------------------------------------------
__global__ void __launch_bounds__(256) round_tf32_kernel(
    const float* __restrict__ inputs, const float* __restrict__ context,
    const float* __restrict__ Wk, const float* __restrict__ Wq)
{
    const int stride = gridDim.x * blockDim.x;
    const int i0 = blockIdx.x * blockDim.x + threadIdx.x;

    const int nIn = BB * TV * DD / 4, nCx = BB * TQ * DD / 4, nW = DD * AA / 4;
    for (int i = i0; i < nIn; i += stride) {
        float4 v = ((const float4*)inputs)[i];
        v.x = round_tf32(v.x); v.y = round_tf32(v.y);
        v.z = round_tf32(v.z); v.w = round_tf32(v.w);
        ((float4*)g_inT)[i] = v;
    }
    for (int i = i0; i < nCx; i += stride) {
        float4 v = ((const float4*)context)[i];
        v.x = round_tf32(v.x); v.y = round_tf32(v.y);
        v.z = round_tf32(v.z); v.w = round_tf32(v.w);
        ((float4*)g_cxT)[i] = v;
    }
    for (int i = i0; i < nW; i += stride) {
        float4 v = ((const float4*)Wk)[i];
        v.x = round_tf32(v.x); v.y = round_tf32(v.y);
        v.z = round_tf32(v.z); v.w = round_tf32(v.w);
        ((float4*)g_WkT)[i] = v;
        float4 u = ((const float4*)Wq)[i];
        u.x = round_tf32(u.x); u.y = round_tf32(u.y);
        u.z = round_tf32(u.z); u.w = round_tf32(u.w);
        ((float4*)g_WqT)[i] = u;
    }
}

// ---------------------------------------------------------------------------
// Shared tf32 GEMM tile body v2: 64 threads = 2 warps stacked on M.
// CTA tile 32(M) x 64(N); warp tile 16 x 64 (nt = 8 n8-frags, A reused 8x).
// Inputs must already be tf32-rounded; fragments feed raw bits to mma.
// As[2][32][36] (m,k); Bs[2][32][72] (k,n). cp.async double-buffered.
// ---------------------------------------------------------------------------
#define AS_STRIDE 36
#define BS_STRIDE 72

struct MmaSmem {
    float As[2][32][AS_STRIDE];
    float Bs[2][32][BS_STRIDE];
};

__device__ __forceinline__ void gemm_tile_tf32(
    MmaSmem* s,
    const float* __restrict__ A, int lda,
    const float* __restrict__ B, int ldb,
    float* __restrict__ out, int ldo,
    const float* __restrict__ bias,    // may be nullptr
    int m0, int n0, int nchunks)
{
    const int t    = threadIdx.x;      // 0..63
    const int lane = t & 31;
    const int gID  = lane >> 2;        // 0..7
    const int tig  = lane & 3;         // 0..3
    const int wm   = t >> 5;           // 0,1  (warp = m-half)

    float4 acc[8] = {};

    // prologue: chunk 0 -> buffer 0
    {
#pragma unroll
        for (int i = 0; i < 4; ++i) {             // As: 256 f4, 4/thr
            int f = i * 64 + t, row = f >> 3, c4 = (f & 7) * 4;
            cp16(&s->As[0][row][c4], &A[(size_t)(m0 + row) * lda + c4]);
        }
#pragma unroll
        for (int i = 0; i < 8; ++i) {             // Bs: 512 f4, 8/thr
            int f = i * 64 + t, row = f >> 4, c4 = (f & 15) * 4;
            cp16(&s->Bs[0][row][c4], &B[(size_t)row * ldb + n0 + c4]);
        }
        cp_commit();
        cp_wait0();
    }
    __syncthreads();

    for (int kc = 0; kc < nchunks; ++kc) {
        const int cur = kc & 1;
        const bool has_next = (kc + 1 < nchunks);
        if (has_next) {
            const int k0 = (kc + 1) * 32;
            const int nxt = cur ^ 1;
#pragma unroll
            for (int i = 0; i < 4; ++i) {
                int f = i * 64 + t, row = f >> 3, c4 = (f & 7) * 4;
                cp16(&s->As[nxt][row][c4], &A[(size_t)(m0 + row) * lda + k0 + c4]);
            }
#pragma unroll
            for (int i = 0; i < 8; ++i) {
                int f = i * 64 + t, row = f >> 4, c4 = (f & 15) * 4;
                cp16(&s->Bs[nxt][row][c4], &B[(size_t)(k0 + row) * ldb + n0 + c4]);
            }
            cp_commit();
        }
        const int ar0 = wm * 16 + gID;
#pragma unroll
        for (int k8 = 0; k8 < 32; k8 += 8) {
            uint32_t a0 = __float_as_uint(s->As[cur][ar0][k8 + tig]);
            uint32_t a1 = __float_as_uint(s->As[cur][ar0 + 8][k8 + tig]);
            uint32_t a2 = __float_as_uint(s->As[cur][ar0][k8 + tig + 4]);
            uint32_t a3 = __float_as_uint(s->As[cur][ar0 + 8][k8 + tig + 4]);
#pragma unroll
            for (int nt = 0; nt < 8; ++nt) {
                const int nc = nt * 8 + gID;
                uint32_t b0 = __float_as_uint(s->Bs[cur][k8 + tig][nc]);
                uint32_t b1 = __float_as_uint(s->Bs[cur][k8 + tig + 4][nc]);
                mma_tf32(acc[nt], a0, a1, a2, a3, b0, b1);
            }
        }
        if (has_next) {
            cp_wait0();
            __syncthreads();
        }
    }

    // epilogue: D frag rows (gID, gID+8), cols (2*tig, 2*tig+1) per n8-frag
    const int orow = m0 + wm * 16 + gID;
#pragma unroll
    for (int nt = 0; nt < 8; ++nt) {
        const int col = n0 + nt * 8 + tig * 2;
        float2 bv = make_float2(0.f, 0.f);
        if (bias) bv = *(const float2*)&bias[col - n0 + (n0)];
        float2 lo = make_float2(acc[nt].x + bv.x, acc[nt].y + bv.y);
        float2 hi = make_float2(acc[nt].z + bv.x, acc[nt].w + bv.y);
        *(float2*)&out[(size_t)orow * ldo + col] = lo;
        *(float2*)&out[(size_t)(orow + 8) * ldo + col] = hi;
    }
}

// ---------------------------------------------------------------------------
// Kernel A: fused K/Q projection via tf32 mma (pre-rounded operands).
// grid = 256 + 64 = 320 CTAs, 64 threads.
// ---------------------------------------------------------------------------
#define PROJ_KCTAS 256   // 128 m-blocks x 2 n-blocks

__global__ void __launch_bounds__(64) proj_kernel(
    const float* __restrict__ bk, const float* __restrict__ bq)
{
    __shared__ MmaSmem s;

    const int bx = blockIdx.x;
    const bool isK = (bx < PROJ_KCTAS);
    const int lx = isK ? bx : (bx - PROJ_KCTAS);
    const float* X    = isK ? g_inT : g_cxT;
    const float* W    = isK ? g_WkT : g_WqT;
    const float* bias = isK ? bk : bq;
    float* out        = isK ? g_K : g_Q;
    const int m0 = (lx >> 1) * 32;
    const int n0 = (lx & 1) * 64;

    gemm_tile_tf32(&s, X, DD, W, AA, out, AA, bias, m0, n0, DD / 32);
}

// ---------------------------------------------------------------------------
// Kernel B: scores + softmax (unchanged structure; attn written tf32-rounded).
// ---------------------------------------------------------------------------
#define KS_STRIDE 132
#define SMEMB_FLOATS (2 * 64 * KS_STRIDE + 4 * 128 + 128 + 4 * 1024)

__global__ void __launch_bounds__(256, 2) score_softmax_kernel(
    const int* __restrict__ mask, const float* __restrict__ attn_v)
{
    extern __shared__ float sm[];
    float* Ks  = sm;                         // 2 x 64 x 132
    float* Qs  = Ks + 2 * 64 * KS_STRIDE;    // 512
    float* av  = Qs + 4 * 128;               // 128
    float* sc  = av + 128;                   // 4096

    const int t  = threadIdx.x;
    const int b  = blockIdx.y;
    const int q0 = blockIdx.x * 4;

    if (t < 128) {
        *(float4*)&Qs[t * 4] =
            *(const float4*)&g_Q[((size_t)(b * TQ + q0)) * AA + t * 4];
        av[t] = attn_v[t];
    }

    const int v0 = t & 63;
    const int q  = t >> 6;

    const float* Kb = g_K + (size_t)b * TV * AA;

    {
#pragma unroll
        for (int i = 0; i < 8; ++i) {
            int f = i * 256 + t;
            int row = f >> 5, c4 = (f & 31) * 4;
            cp16(&Ks[row * KS_STRIDE + c4], &Kb[(size_t)row * AA + c4]);
        }
        cp_commit();
        cp_wait0();
    }
    __syncthreads();

    for (int vt = 0; vt < TV / 64; ++vt) {
        const int cur = vt & 1;
        const bool has_next = (vt + 1 < TV / 64);
        if (has_next) {
            const int nxt = cur ^ 1;
            const float* Kp = Kb + (size_t)(vt + 1) * 64 * AA;
            float* Kd = Ks + nxt * 64 * KS_STRIDE;
#pragma unroll
            for (int i = 0; i < 8; ++i) {
                int f = i * 256 + t;
                int row = f >> 5, c4 = (f & 31) * 4;
                cp16(&Kd[row * KS_STRIDE + c4], &Kp[(size_t)row * AA + c4]);
            }
            cp_commit();
        }

        float a0 = 0.f;
        const float* kp = Ks + cur * 64 * KS_STRIDE + v0 * KS_STRIDE;
        const float* qp = Qs + q * AA;
#pragma unroll 4
        for (int a4 = 0; a4 < AA; a4 += 4) {
            float4 k4 = *(const float4*)&kp[a4];
            float4 q4 = *(const float4*)&qp[a4];
            float4 w4 = *(const float4*)&av[a4];
            a0 = fmaf(w4.x, ftanh(q4.x + k4.x), a0);
            a0 = fmaf(w4.y, ftanh(q4.y + k4.y), a0);
            a0 = fmaf(w4.z, ftanh(q4.z + k4.z), a0);
            a0 = fmaf(w4.w, ftanh(q4.w + k4.w), a0);
        }
        sc[q * TV + vt * 64 + v0] = a0;

        if (has_next) {
            cp_wait0();
            __syncthreads();
        }
    }
    __syncthreads();

    const int w = t >> 5, lane = t & 31;
    if (w < 4) {
        float* row = sc + w * TV;
        const int* mrow = mask + (size_t)b * TV;
        float mx = -3.4e38f;
        for (int j = lane; j < TV; j += 32) {
            float s = row[j] + (1.0f - (float)mrow[j]) * (-1e9f);
            row[j] = s;
            mx = fmaxf(mx, s);
        }
#pragma unroll
        for (int o = 16; o; o >>= 1) mx = fmaxf(mx, __shfl_xor_sync(~0u, mx, o));
        float sum = 0.f;
        for (int j = lane; j < TV; j += 32) {
            float e = fast_ex2((row[j] - mx) * 1.4426950408889634f);
            row[j] = e;
            sum += e;
        }
#pragma unroll
        for (int o = 16; o; o >>= 1) sum += __shfl_xor_sync(~0u, sum, o);
        float inv = 1.0f / sum;
        float* arow = g_attn + ((size_t)(b * TQ + q0 + w)) * TV;
        // write attn tf32-rounded so av_kernel can feed raw bits to mma
        for (int j = lane; j < TV; j += 32) arow[j] = round_tf32(row[j] * inv);
    }
}

// ---------------------------------------------------------------------------
// Kernel C: out = attn @ inputs via tf32 mma (pre-rounded operands).
// grid (DD/64=8, TQ/32=8, BB=4) = 256 CTAs, 64 threads.
// ---------------------------------------------------------------------------
__global__ void __launch_bounds__(64) av_kernel(float* __restrict__ out)
{
    __shared__ MmaSmem s;

    const int b  = blockIdx.z;
    const int m0 = blockIdx.y * 32;
    const int n0 = blockIdx.x * 64;

    const float* A = g_attn + (size_t)b * TQ * TV;   // [256, 1024] tf32
    const float* B = g_inT  + (size_t)b * TV * DD;   // [1024, 512] tf32
    float* O       = out    + (size_t)b * TQ * DD;   // [256, 512]

    gemm_tile_tf32(&s, A, TV, B, DD, O, DD, nullptr, m0, n0, TV / 32);
}

// ---------------------------------------------------------------------------
extern "C" void kernel_launch(void* const* d_in, const int* in_sizes, int n_in,
                              void* d_out, int out_size)
{
    (void)in_sizes; (void)n_in; (void)out_size;
    const float* inputs  = (const float*)d_in[0];   // [B,Tv,D]
    const float* context = (const float*)d_in[1];   // [B,Tq,D]
    const int*   mask    = (const int*)  d_in[2];   // [B,Tv]
    const float* Wk      = (const float*)d_in[3];   // [D,A]
    const float* bk      = (const float*)d_in[4];   // [A]
    const float* Wq      = (const float*)d_in[5];   // [D,A]
    const float* bq      = (const float*)d_in[6];   // [A]
    const float* attn_v  = (const float*)d_in[7];   // [A]
    float* out = (float*)d_out;                     // [B,Tq,D]

    static const size_t smemB = SMEMB_FLOATS * sizeof(float);
    cudaFuncSetAttribute(score_softmax_kernel,
                         cudaFuncAttributeMaxDynamicSharedMemorySize, (int)smemB);

    // 0) round mma operands to tf32 once
    round_tf32_kernel<<<592, 256>>>(inputs, context, Wk, Wq);
    // 1) K/Q projection (tf32 mma, 320 CTAs x 64 thr)
    proj_kernel<<<PROJ_KCTAS + 64, 64>>>(bk, bq);
    // 2) scores + softmax -> g_attn (tf32-rounded)
    {
        dim3 grid(TQ / 4, BB);
        score_softmax_kernel<<<grid, 256, smemB>>>(mask, attn_v);
    }
    // 3) out = attn @ inputs (tf32 mma, 256 CTAs x 64 thr)
    {
        dim3 grid(DD / 64, TQ / 32, BB);
        av_kernel<<<grid, 64>>>(out);
    }
}

// round 17
// speedup vs baseline: 1.0123x; 1.0123x over previous
#include <cuda_runtime.h>
#include <cuda_bf16.h>
#include <cstdint>

// Problem dims (fixed by the dataset)
#define BB   4
#define TQ   256
#define TV   1024
#define DD   512
#define AA   128

// Scratch buffers (device globals: allocation-free)
__device__ float g_K[BB * TV * AA];        // 2 MB
__device__ float g_Q[BB * TQ * AA];        // 0.5 MB
__device__ float g_attn[BB * TQ * TV];     // 4 MB (tf32-rounded at write)
__device__ float g_inT[BB * TV * DD];      // 8 MB   inputs, tf32-rounded
__device__ float g_cxT[BB * TQ * DD];      // 2 MB   context, tf32-rounded
__device__ float g_WkT[DD * AA];           // 256 KB
__device__ float g_WqT[DD * AA];           // 256 KB

// ---------------------------------------------------------------------------
// fast math helpers
// ---------------------------------------------------------------------------
__device__ __forceinline__ float fast_ex2(float x) {
    float y;
    asm("ex2.approx.f32 %0, %1;" : "=f"(y) : "f"(x));
    return y;
}
__device__ __forceinline__ float ftanh(float x) {
    float y;
    asm("tanh.approx.f32 %0, %1;" : "=f"(y) : "f"(x));
    return y;
}
// cp.async helpers (16B)
__device__ __forceinline__ void cp16(void* dst_smem, const void* src_gmem) {
    unsigned d = (unsigned)__cvta_generic_to_shared(dst_smem);
    asm volatile("cp.async.ca.shared.global [%0], [%1], 16;" :: "r"(d), "l"(src_gmem));
}
__device__ __forceinline__ void cp_commit() {
    asm volatile("cp.async.commit_group;");
}
__device__ __forceinline__ void cp_wait0() {
    asm volatile("cp.async.wait_group 0;");
}
// tf32 round (rna)
__device__ __forceinline__ float round_tf32(float x) {
    uint32_t r;
    asm("cvt.rna.tf32.f32 %0, %1;" : "=r"(r) : "f"(x));
    return __uint_as_float(r);
}
__device__ __forceinline__ void mma_tf32(float4& d,
    uint32_t a0, uint32_t a1, uint32_t a2, uint32_t a3,
    uint32_t b0, uint32_t b1)
{
    asm volatile(
        "mma.sync.aligned.m16n8k8.row.col.f32.tf32.tf32.f32 "
        "{%0,%1,%2,%3}, {%4,%5,%6,%7}, {%8,%9}, {%0,%1,%2,%3};"
        : "+f"(d.x), "+f"(d.y), "+f"(d.z), "+f"(d.w)
        : "r"(a0), "r"(a1), "r"(a2), "r"(a3), "r"(b0), "r"(b1));
}

// ---------------------------------------------------------------------------
// Kernel 0: round inputs/context/Wk/Wq to tf32 (rna) once, so GEMM mainloops
// feed raw register bits to mma (bit-exact tf32, zero per-use cvt).
// ---------------------------------------------------------------------------
__global__ void __launch_bounds__(256) round_tf32_kernel(
    const float* __restrict__ inputs, const float* __restrict__ context,
    const float* __restrict__ Wk, const float* __restrict__ Wq)
{
    const int stride = gridDim.x * blockDim.x;
    const int i0 = blockIdx.x * blockDim.x + threadIdx.x;

    const int nIn = BB * TV * DD / 4, nCx = BB * TQ * DD / 4, nW = DD * AA / 4;
    for (int i = i0; i < nIn; i += stride) {
        float4 v = ((const float4*)inputs)[i];
        v.x = round_tf32(v.x); v.y = round_tf32(v.y);
        v.z = round_tf32(v.z); v.w = round_tf32(v.w);
        ((float4*)g_inT)[i] = v;
    }
    for (int i = i0; i < nCx; i += stride) {
        float4 v = ((const float4*)context)[i];
        v.x = round_tf32(v.x); v.y = round_tf32(v.y);
        v.z = round_tf32(v.z); v.w = round_tf32(v.w);
        ((float4*)g_cxT)[i] = v;
    }
    for (int i = i0; i < nW; i += stride) {
        float4 v = ((const float4*)Wk)[i];
        v.x = round_tf32(v.x); v.y = round_tf32(v.y);
        v.z = round_tf32(v.z); v.w = round_tf32(v.w);
        ((float4*)g_WkT)[i] = v;
        float4 u = ((const float4*)Wq)[i];
        u.x = round_tf32(u.x); u.y = round_tf32(u.y);
        u.z = round_tf32(u.z); u.w = round_tf32(u.w);
        ((float4*)g_WqT)[i] = u;
    }
}

// ---------------------------------------------------------------------------
// Shared tf32 GEMM tile body (R15 shape, pre-rounded operands):
// CTA = 128 threads = 2x2 warps; CTA tile 32(M) x 64(N); warp tile 16x32
// (nt = 4 n8-frags). K in 32-chunks, cp.async double-buffered.
// As[2][32][36] (m,k); Bs[2][32][72] (k,n).
// ---------------------------------------------------------------------------
#define AS_STRIDE 36
#define BS_STRIDE 72

struct MmaSmem {
    float As[2][32][AS_STRIDE];
    float Bs[2][32][BS_STRIDE];
};

__device__ __forceinline__ void gemm_tile_tf32(
    MmaSmem* s,
    const float* __restrict__ A, int lda,
    const float* __restrict__ B, int ldb,
    float* __restrict__ out, int ldo,
    const float* __restrict__ bias,    // may be nullptr
    int m0, int n0, int nchunks)
{
    const int t    = threadIdx.x;
    const int lane = t & 31;
    const int gID  = lane >> 2;      // 0..7
    const int tig  = lane & 3;       // 0..3
    const int wm   = (t >> 5) >> 1;  // 0,1
    const int wn   = (t >> 5) & 1;   // 0,1

    // fill coords
    // As: 32 rows x 32 floats = 256 f4; ar in [0,16), +16 second half
    const int ar = t >> 3, ac4 = (t & 7) * 4;
    // Bs: 32 rows x 64 floats = 512 f4; br in [0,8), +8/+16/+24
    const int br = t >> 4, bc4 = (t & 15) * 4;

    float4 acc[4] = {};

    // prologue: chunk 0 -> buffer 0
    {
        cp16(&s->As[0][ar][ac4],      &A[(size_t)(m0 + ar) * lda + ac4]);
        cp16(&s->As[0][ar + 16][ac4], &A[(size_t)(m0 + ar + 16) * lda + ac4]);
#pragma unroll
        for (int i = 0; i < 4; ++i)
            cp16(&s->Bs[0][br + i * 8][bc4],
                 &B[(size_t)(br + i * 8) * ldb + n0 + bc4]);
        cp_commit();
        cp_wait0();
    }
    __syncthreads();

    for (int kc = 0; kc < nchunks; ++kc) {
        const int cur = kc & 1;
        const bool has_next = (kc + 1 < nchunks);
        if (has_next) {
            const int k0 = (kc + 1) * 32;
            const int nxt = cur ^ 1;
            cp16(&s->As[nxt][ar][ac4],      &A[(size_t)(m0 + ar) * lda + k0 + ac4]);
            cp16(&s->As[nxt][ar + 16][ac4], &A[(size_t)(m0 + ar + 16) * lda + k0 + ac4]);
#pragma unroll
            for (int i = 0; i < 4; ++i)
                cp16(&s->Bs[nxt][br + i * 8][bc4],
                     &B[(size_t)(k0 + br + i * 8) * ldb + n0 + bc4]);
            cp_commit();
        }
        const int ar0 = wm * 16 + gID;
#pragma unroll
        for (int k8 = 0; k8 < 32; k8 += 8) {
            uint32_t a0 = __float_as_uint(s->As[cur][ar0][k8 + tig]);
            uint32_t a1 = __float_as_uint(s->As[cur][ar0 + 8][k8 + tig]);
            uint32_t a2 = __float_as_uint(s->As[cur][ar0][k8 + tig + 4]);
            uint32_t a3 = __float_as_uint(s->As[cur][ar0 + 8][k8 + tig + 4]);
#pragma unroll
            for (int nt = 0; nt < 4; ++nt) {
                const int nc = wn * 32 + nt * 8 + gID;
                uint32_t b0 = __float_as_uint(s->Bs[cur][k8 + tig][nc]);
                uint32_t b1 = __float_as_uint(s->Bs[cur][k8 + tig + 4][nc]);
                mma_tf32(acc[nt], a0, a1, a2, a3, b0, b1);
            }
        }
        if (has_next) {
            cp_wait0();
            __syncthreads();
        }
    }

    // epilogue: D frag rows (gID, gID+8), cols (2*tig, 2*tig+1)
    const int orow = m0 + wm * 16 + gID;
#pragma unroll
    for (int nt = 0; nt < 4; ++nt) {
        const int col = n0 + wn * 32 + nt * 8 + tig * 2;
        float2 bv = make_float2(0.f, 0.f);
        if (bias) bv = *(const float2*)&bias[col];
        float2 lo = make_float2(acc[nt].x + bv.x, acc[nt].y + bv.y);
        float2 hi = make_float2(acc[nt].z + bv.x, acc[nt].w + bv.y);
        *(float2*)&out[(size_t)orow * ldo + col] = lo;
        *(float2*)&out[(size_t)(orow + 8) * ldo + col] = hi;
    }
}

// ---------------------------------------------------------------------------
// Kernel A: fused K/Q projection via tf32 mma (pre-rounded operands).
// CTA tile 32x64 -> grid = 256 + 64 = 320 CTAs, 128 threads.
// ---------------------------------------------------------------------------
#define PROJ_KCTAS 256   // 128 m-blocks x 2 n-blocks

__global__ void __launch_bounds__(128) proj_kernel(
    const float* __restrict__ bk, const float* __restrict__ bq)
{
    __shared__ MmaSmem s;

    const int bx = blockIdx.x;
    const bool isK = (bx < PROJ_KCTAS);
    const int lx = isK ? bx : (bx - PROJ_KCTAS);
    const float* X    = isK ? g_inT : g_cxT;
    const float* W    = isK ? g_WkT : g_WqT;
    const float* bias = isK ? bk : bq;
    float* out        = isK ? g_K : g_Q;
    const int m0 = (lx >> 1) * 32;
    const int n0 = (lx & 1) * 64;

    gemm_tile_tf32(&s, X, DD, W, AA, out, AA, bias, m0, n0, DD / 32);
}

// ---------------------------------------------------------------------------
// Kernel B: scores + softmax (attn written tf32-rounded).
// ---------------------------------------------------------------------------
#define KS_STRIDE 132
#define SMEMB_FLOATS (2 * 64 * KS_STRIDE + 4 * 128 + 128 + 4 * 1024)

__global__ void __launch_bounds__(256, 2) score_softmax_kernel(
    const int* __restrict__ mask, const float* __restrict__ attn_v)
{
    extern __shared__ float sm[];
    float* Ks  = sm;                         // 2 x 64 x 132
    float* Qs  = Ks + 2 * 64 * KS_STRIDE;    // 512
    float* av  = Qs + 4 * 128;               // 128
    float* sc  = av + 128;                   // 4096

    const int t  = threadIdx.x;
    const int b  = blockIdx.y;
    const int q0 = blockIdx.x * 4;

    if (t < 128) {
        *(float4*)&Qs[t * 4] =
            *(const float4*)&g_Q[((size_t)(b * TQ + q0)) * AA + t * 4];
        av[t] = attn_v[t];
    }

    const int v0 = t & 63;
    const int q  = t >> 6;

    const float* Kb = g_K + (size_t)b * TV * AA;

    {
#pragma unroll
        for (int i = 0; i < 8; ++i) {
            int f = i * 256 + t;
            int row = f >> 5, c4 = (f & 31) * 4;
            cp16(&Ks[row * KS_STRIDE + c4], &Kb[(size_t)row * AA + c4]);
        }
        cp_commit();
        cp_wait0();
    }
    __syncthreads();

    for (int vt = 0; vt < TV / 64; ++vt) {
        const int cur = vt & 1;
        const bool has_next = (vt + 1 < TV / 64);
        if (has_next) {
            const int nxt = cur ^ 1;
            const float* Kp = Kb + (size_t)(vt + 1) * 64 * AA;
            float* Kd = Ks + nxt * 64 * KS_STRIDE;
#pragma unroll
            for (int i = 0; i < 8; ++i) {
                int f = i * 256 + t;
                int row = f >> 5, c4 = (f & 31) * 4;
                cp16(&Kd[row * KS_STRIDE + c4], &Kp[(size_t)row * AA + c4]);
            }
            cp_commit();
        }

        float a0 = 0.f;
        const float* kp = Ks + cur * 64 * KS_STRIDE + v0 * KS_STRIDE;
        const float* qp = Qs + q * AA;
#pragma unroll 4
        for (int a4 = 0; a4 < AA; a4 += 4) {
            float4 k4 = *(const float4*)&kp[a4];
            float4 q4 = *(const float4*)&qp[a4];
            float4 w4 = *(const float4*)&av[a4];
            a0 = fmaf(w4.x, ftanh(q4.x + k4.x), a0);
            a0 = fmaf(w4.y, ftanh(q4.y + k4.y), a0);
            a0 = fmaf(w4.z, ftanh(q4.z + k4.z), a0);
            a0 = fmaf(w4.w, ftanh(q4.w + k4.w), a0);
        }
        sc[q * TV + vt * 64 + v0] = a0;

        if (has_next) {
            cp_wait0();
            __syncthreads();
        }
    }
    __syncthreads();

    const int w = t >> 5, lane = t & 31;
    if (w < 4) {
        float* row = sc + w * TV;
        const int* mrow = mask + (size_t)b * TV;
        float mx = -3.4e38f;
        for (int j = lane; j < TV; j += 32) {
            float s = row[j] + (1.0f - (float)mrow[j]) * (-1e9f);
            row[j] = s;
            mx = fmaxf(mx, s);
        }
#pragma unroll
        for (int o = 16; o; o >>= 1) mx = fmaxf(mx, __shfl_xor_sync(~0u, mx, o));
        float sum = 0.f;
        for (int j = lane; j < TV; j += 32) {
            float e = fast_ex2((row[j] - mx) * 1.4426950408889634f);
            row[j] = e;
            sum += e;
        }
#pragma unroll
        for (int o = 16; o; o >>= 1) sum += __shfl_xor_sync(~0u, sum, o);
        float inv = 1.0f / sum;
        float* arow = g_attn + ((size_t)(b * TQ + q0 + w)) * TV;
        // write attn tf32-rounded so av_kernel can feed raw bits to mma
        for (int j = lane; j < TV; j += 32) arow[j] = round_tf32(row[j] * inv);
    }
}

// ---------------------------------------------------------------------------
// Kernel C: out = attn @ inputs via tf32 mma (pre-rounded operands).
// grid (DD/64=8, TQ/32=8, BB=4) = 256 CTAs, 128 threads.
// ---------------------------------------------------------------------------
__global__ void __launch_bounds__(128) av_kernel(float* __restrict__ out)
{
    __shared__ MmaSmem s;

    const int b  = blockIdx.z;
    const int m0 = blockIdx.y * 32;
    const int n0 = blockIdx.x * 64;

    const float* A = g_attn + (size_t)b * TQ * TV;   // [256, 1024] tf32
    const float* B = g_inT  + (size_t)b * TV * DD;   // [1024, 512] tf32
    float* O       = out    + (size_t)b * TQ * DD;   // [256, 512]

    gemm_tile_tf32(&s, A, TV, B, DD, O, DD, nullptr, m0, n0, TV / 32);
}

// ---------------------------------------------------------------------------
extern "C" void kernel_launch(void* const* d_in, const int* in_sizes, int n_in,
                              void* d_out, int out_size)
{
    (void)in_sizes; (void)n_in; (void)out_size;
    const float* inputs  = (const float*)d_in[0];   // [B,Tv,D]
    const float* context = (const float*)d_in[1];   // [B,Tq,D]
    const int*   mask    = (const int*)  d_in[2];   // [B,Tv]
    const float* Wk      = (const float*)d_in[3];   // [D,A]
    const float* bk      = (const float*)d_in[4];   // [A]
    const float* Wq      = (const float*)d_in[5];   // [D,A]
    const float* bq      = (const float*)d_in[6];   // [A]
    const float* attn_v  = (const float*)d_in[7];   // [A]
    float* out = (float*)d_out;                     // [B,Tq,D]

    static const size_t smemB = SMEMB_FLOATS * sizeof(float);
    cudaFuncSetAttribute(score_softmax_kernel,
                         cudaFuncAttributeMaxDynamicSharedMemorySize, (int)smemB);

    // 0) round mma operands to tf32 once
    round_tf32_kernel<<<592, 256>>>(inputs, context, Wk, Wq);
    // 1) K/Q projection (tf32 mma, 320 CTAs x 128 thr)
    proj_kernel<<<PROJ_KCTAS + 64, 128>>>(bk, bq);
    // 2) scores + softmax -> g_attn (tf32-rounded)
    {
        dim3 grid(TQ / 4, BB);
        score_softmax_kernel<<<grid, 256, smemB>>>(mask, attn_v);
    }
    // 3) out = attn @ inputs (tf32 mma, 256 CTAs x 128 thr)
    {
        dim3 grid(DD / 64, TQ / 32, BB);
        av_kernel<<<grid, 128>>>(out);
    }
}